// round 9
// baseline (speedup 1.0000x reference)
#include <cuda_runtime.h>
#include <cstdint>

#define BB 8
#define SEQ 1024
#define DM 512
#define NH 8
#define DK 64

// Scratch (allocation-free rule: __device__ globals).
__device__ float g_q[BB * NH * SEQ * DK];
__device__ float g_k[BB * NH * SEQ * DK];
__device__ float g_v[BB * NH * SEQ * DK];
__device__ float g_hd[BB * SEQ * DM];
__device__ uint8_t g_mask8[(size_t)BB * SEQ * SEQ];
__device__ unsigned g_flags[2];

// ===========================================================================
// tf32 helpers (baseline PTX, supported on plain sm_103 target)
// ===========================================================================
__device__ __forceinline__ uint32_t f2tf32(float f) {
    uint32_t u;
    asm("cvt.rna.tf32.f32 %0, %1;" : "=r"(u) : "f"(f));
    return u;
}

__device__ __forceinline__ void mma_tf32(float* c, const uint32_t* a,
                                         const uint32_t* b) {
    asm volatile(
        "mma.sync.aligned.m16n8k8.row.col.f32.tf32.tf32.f32 "
        "{%0,%1,%2,%3}, {%4,%5,%6,%7}, {%8,%9}, {%0,%1,%2,%3};"
        : "+f"(c[0]), "+f"(c[1]), "+f"(c[2]), "+f"(c[3])
        : "r"(a[0]), "r"(a[1]), "r"(a[2]), "r"(a[3]),
          "r"(b[0]), "r"(b[1]));
}

// ===========================================================================
// Mask dtype detection + canonicalization (proven).
// ===========================================================================
__global__ void mask_detect(const unsigned* __restrict__ m)
{
    __shared__ unsigned s0, s1;
    if (threadIdx.x == 0) { s0 = 0u; s1 = 0u; }
    __syncthreads();
    unsigned a0 = 0u, a1 = 0u;
    for (int i = threadIdx.x; i < 65536; i += blockDim.x) {
        const unsigned w = m[i];
        if (w > 1u) a0 = 1u;
        const unsigned b = w | (w >> 8) | (w >> 16) | (w >> 24);
        if (b & 0xFEu) a1 = 1u;
    }
    if (a0) atomicOr(&s0, 1u);
    if (a1) atomicOr(&s1, 1u);
    __syncthreads();
    if (threadIdx.x == 0) { g_flags[0] = s0; g_flags[1] = s1; }
}

__global__ __launch_bounds__(256) void mask_convert(const void* __restrict__ mraw)
{
    const size_t i = (size_t)blockIdx.x * 256 + threadIdx.x;
    const unsigned kind = (g_flags[0] == 0u) ? 0u : ((g_flags[1] == 0u) ? 1u : 2u);
    uchar4 o;
    if (kind == 0u) {
        const int4 v = reinterpret_cast<const int4*>(mraw)[i];
        o.x = (v.x != 0); o.y = (v.y != 0); o.z = (v.z != 0); o.w = (v.w != 0);
    } else if (kind == 1u) {
        o = reinterpret_cast<const uchar4*>(mraw)[i];
    } else {
        const float4 v = reinterpret_cast<const float4*>(mraw)[i];
        o.x = (v.x != 0.0f); o.y = (v.y != 0.0f);
        o.z = (v.z != 0.0f); o.w = (v.w != 0.0f);
    }
    reinterpret_cast<uchar4*>(g_mask8)[i] = o;
}

// ===========================================================================
// Warp-level mma.sync tf32 GEMM for projections (proven in R5; unchanged).
// ===========================================================================
__global__ __launch_bounds__(256) void gemm_mma(
    const float* __restrict__ x,
    const float* __restrict__ Wq, const float* __restrict__ Wk,
    const float* __restrict__ Wv, const float* __restrict__ Wo,
    float* __restrict__ outp, int mode)
{
    __shared__ uint32_t As[128][36];
    __shared__ uint32_t Bs[64][36];

    const int tid = threadIdx.x;
    const int wid = tid >> 5;
    const int lid = tid & 31;
    const int wm = wid & 3;
    const int wn = wid >> 2;
    const int g = lid >> 2;
    const int t = lid & 3;

    const float* __restrict__ A;
    const float* __restrict__ Bb;
    int ldb;
    if (mode == 0) {
        const int z = blockIdx.z;
        const float* W = (z == 0) ? Wq : ((z == 1) ? Wk : Wv);
        A = x;
        Bb = W + (size_t)blockIdx.y * DM * DK;
        ldb = DK;
    } else {
        A = g_hd;
        Bb = Wo + blockIdx.y * 64;
        ldb = DM;
    }
    const int m0 = blockIdx.x * 128;

    float acc[2][4][4];
#pragma unroll
    for (int i = 0; i < 2; i++)
#pragma unroll
        for (int j = 0; j < 4; j++)
#pragma unroll
            for (int e = 0; e < 4; e++) acc[i][j][e] = 0.0f;

    for (int k0 = 0; k0 < DM; k0 += 32) {
#pragma unroll
        for (int it = 0; it < 4; it++) {
            const int idx = it * 256 + tid;
            const int r = idx >> 3;
            const int q = idx & 7;
            const float4 v = *reinterpret_cast<const float4*>(
                &A[(size_t)(m0 + r) * DM + k0 + q * 4]);
            uint4 u = make_uint4(f2tf32(v.x), f2tf32(v.y),
                                 f2tf32(v.z), f2tf32(v.w));
            *reinterpret_cast<uint4*>(&As[r][q * 4]) = u;
        }
#pragma unroll
        for (int it = 0; it < 2; it++) {
            const int idx = it * 256 + tid;
            const int kk = idx >> 4;
            const int nq = idx & 15;
            const float4 v = *reinterpret_cast<const float4*>(
                &Bb[(size_t)(k0 + kk) * ldb + nq * 4]);
            Bs[nq * 4 + 0][kk] = f2tf32(v.x);
            Bs[nq * 4 + 1][kk] = f2tf32(v.y);
            Bs[nq * 4 + 2][kk] = f2tf32(v.z);
            Bs[nq * 4 + 3][kk] = f2tf32(v.w);
        }
        __syncthreads();

#pragma unroll
        for (int kk = 0; kk < 4; kk++) {
            const int kb = kk * 8;
            uint32_t bf[4][2];
#pragma unroll
            for (int j = 0; j < 4; j++) {
                const int n = wn * 32 + j * 8 + g;
                bf[j][0] = Bs[n][kb + t];
                bf[j][1] = Bs[n][kb + t + 4];
            }
#pragma unroll
            for (int i = 0; i < 2; i++) {
                const int r0 = wm * 32 + i * 16 + g;
                uint32_t af[4];
                af[0] = As[r0][kb + t];
                af[1] = As[r0 + 8][kb + t];
                af[2] = As[r0][kb + t + 4];
                af[3] = As[r0 + 8][kb + t + 4];
#pragma unroll
                for (int j = 0; j < 4; j++)
                    mma_tf32(acc[i][j], af, bf[j]);
            }
        }
        __syncthreads();
    }

#pragma unroll
    for (int i = 0; i < 2; i++) {
#pragma unroll
        for (int rr = 0; rr < 2; rr++) {
            const int mg = m0 + wm * 32 + i * 16 + rr * 8 + g;
            float* dst;
            if (mode == 0) {
                const int z = blockIdx.z;
                float* outg = (z == 0) ? g_q : ((z == 1) ? g_k : g_v);
                const int b = mg >> 10;
                const int n = mg & 1023;
                dst = &outg[(((size_t)b * NH + blockIdx.y) * SEQ + n) * DK];
            } else {
                dst = &outp[(size_t)mg * DM + blockIdx.y * 64];
            }
#pragma unroll
            for (int j = 0; j < 4; j++) {
                const int col = wn * 32 + j * 8 + t * 2;
                float2 o2 = make_float2(acc[i][j][rr * 2 + 0],
                                        acc[i][j][rr * 2 + 1]);
                *reinterpret_cast<float2*>(&dst[col]) = o2;
            }
        }
    }
}

// ===========================================================================
// Flash attention, mma.sync tf32 — 2 m-atoms/warp, Q in SMEM, P via shuffle.
// CTA = 128 q-rows, 4 warps x 32 rows, 128 threads.
// R8 lesson: 2 CTAs/SM (smem-bound) erased the spill fix. Deleting the P
// smem buffer (34.8 KB) via intra-quad shuffles gets 69.6 KB -> 3 CTAs/SM.
// PV A-frag word P(row g, col 8ks+t) lives at lane (g*4 + (t>>1)),
// element (t&1) of the quad that computed it -> 2 shfl + 1 select per word.
// ===========================================================================
#define QS_OFF 0                      // [128][68] u32 : Q (tf32, pre-scaled)
#define KS_OFF (128 * 68)             // [64][68]  u32 : K tile [key][d]
#define VT_OFF (KS_OFF + 64 * 68)     // [64][68]  u32 : V tile [d][key]
#define ATT_SMEM ((VT_OFF + 64 * 68) * 4)   // 69632 B -> 3 CTAs/SM

// Build one PV A-frag word: value P(row_sel, col 8ks + t + off) for this
// lane's (g, t), from quad-mate src; e0/e1 = the two column-parity regs.
__device__ __forceinline__ uint32_t pfrag(float e0, float e1, int src, int t) {
    const float v0 = __shfl_sync(0xffffffffu, e0, src);
    const float v1 = __shfl_sync(0xffffffffu, e1, src);
    return __float_as_uint((t & 1) ? v1 : v0);
}

__global__ __launch_bounds__(128, 3) void attn_kernel()
{
    extern __shared__ uint32_t dsm[];
    uint32_t* __restrict__ Qs = dsm + QS_OFF;
    uint32_t* __restrict__ Ks = dsm + KS_OFF;
    uint32_t* __restrict__ Vt = dsm + VT_OFF;

    const int r0 = blockIdx.x * 128;
    const int h  = blockIdx.y;
    const int b  = blockIdx.z;

    const int tid = threadIdx.x;
    const int w   = tid >> 5;
    const int lid = tid & 31;
    const int g   = lid >> 2;
    const int t   = lid & 3;
    const int wr  = w * 32;            // warp row base (local, 32 rows)

    const size_t bh = (size_t)b * NH + h;
    const float* __restrict__ Qg = &g_q[bh * SEQ * DK];
    const float* __restrict__ Kg = &g_k[bh * SEQ * DK];
    const float* __restrict__ Vg = &g_v[bh * SEQ * DK];
    const uint8_t* __restrict__ Mg = &g_mask8[(size_t)b * SEQ * SEQ];

    // --- Stage Q tile (pre-scaled by 1/sqrt(64) = 0.125, exact in tf32).
#pragma unroll
    for (int it = 0; it < 16; it++) {
        const int idx = it * 128 + tid;
        const int r = idx >> 4;
        const int q4 = idx & 15;
        const float4 v = *reinterpret_cast<const float4*>(
            &Qg[(size_t)(r0 + r) * DK + q4 * 4]);
        uint4 u = make_uint4(f2tf32(v.x * 0.125f), f2tf32(v.y * 0.125f),
                             f2tf32(v.z * 0.125f), f2tf32(v.w * 0.125f));
        *reinterpret_cast<uint4*>(&Qs[r * 68 + q4 * 4]) = u;
    }
    __syncthreads();

    // Q fragment row bases for this thread (4 m16-atom rows).
    const int ra = (wr + g) * 68;
    const int rb = ra + 8 * 68;
    const int rc = ra + 16 * 68;
    const int rd = ra + 24 * 68;

    // Shuffle source lanes for the PV A-frags (quad-internal).
    const int srcA = (lid & ~3) + (t >> 1);
    const int srcB = srcA + 2;

    // Online softmax state per thread: 4 owned rows (2 atoms x {g, g+8}).
    float mi[2][2], li[2][2];
#pragma unroll
    for (int a = 0; a < 2; a++) {
        mi[a][0] = -1e30f; mi[a][1] = -1e30f;
        li[a][0] = 0.0f;   li[a][1] = 0.0f;
    }
    float oc[2][8][4];
#pragma unroll
    for (int a = 0; a < 2; a++)
#pragma unroll
        for (int j = 0; j < 8; j++)
#pragma unroll
            for (int e = 0; e < 4; e++) oc[a][j][e] = 0.0f;

    for (int m0 = 0; m0 < SEQ; m0 += 64) {
        // K tile: natural [key][d] layout (coalesced).
#pragma unroll
        for (int it = 0; it < 8; it++) {
            const int idx = it * 128 + tid;
            const int r = idx >> 4;
            const int q4 = idx & 15;
            const float4 v = *reinterpret_cast<const float4*>(
                &Kg[(size_t)(m0 + r) * DK + q4 * 4]);
            uint4 u = make_uint4(f2tf32(v.x), f2tf32(v.y),
                                 f2tf32(v.z), f2tf32(v.w));
            *reinterpret_cast<uint4*>(&Ks[r * 68 + q4 * 4]) = u;
        }
        // V tile transposed: Vt[d][key].
#pragma unroll
        for (int it = 0; it < 8; it++) {
            const int idx = it * 128 + tid;
            const int key = idx & 63;
            const int dq = idx >> 6;
            const float4 v = *reinterpret_cast<const float4*>(
                &Vg[(size_t)(m0 + key) * DK + dq * 4]);
            Vt[(dq * 4 + 0) * 68 + key] = f2tf32(v.x);
            Vt[(dq * 4 + 1) * 68 + key] = f2tf32(v.y);
            Vt[(dq * 4 + 2) * 68 + key] = f2tf32(v.z);
            Vt[(dq * 4 + 3) * 68 + key] = f2tf32(v.w);
        }
        __syncthreads();

        // ---- S = Q K^T : Q frags from SMEM per ks (shared by both atoms),
        //      one bf load feeds both m-atoms.
        float sacc[2][8][4];
#pragma unroll
        for (int a = 0; a < 2; a++)
#pragma unroll
            for (int j = 0; j < 8; j++)
#pragma unroll
                for (int e = 0; e < 4; e++) sacc[a][j][e] = 0.0f;

#pragma unroll
        for (int ks = 0; ks < 8; ks++) {
            const int kb = ks * 8;
            uint32_t aq[8];
            aq[0] = Qs[ra + kb + t];
            aq[1] = Qs[rb + kb + t];
            aq[2] = Qs[ra + kb + t + 4];
            aq[3] = Qs[rb + kb + t + 4];
            aq[4] = Qs[rc + kb + t];
            aq[5] = Qs[rd + kb + t];
            aq[6] = Qs[rc + kb + t + 4];
            aq[7] = Qs[rd + kb + t + 4];
#pragma unroll
            for (int j = 0; j < 8; j++) {
                uint32_t bf[2];
                bf[0] = Ks[(j * 8 + g) * 68 + kb + t];
                bf[1] = Ks[(j * 8 + g) * 68 + kb + t + 4];
                mma_tf32(sacc[0][j], aq, bf);
                mma_tf32(sacc[1][j], aq + 4, bf);
            }
        }

        // ---- mask + online softmax per atom; leave tf32(P) bits in sacc.
#pragma unroll
        for (int a = 0; a < 2; a++) {
            const int gr_lo = r0 + wr + g + a * 16;
            const int gr_hi = gr_lo + 8;
#pragma unroll
            for (int j = 0; j < 8; j++) {
                const int col = m0 + j * 8 + 2 * t;
                const uchar2 mlo = *reinterpret_cast<const uchar2*>(
                    &Mg[(size_t)gr_lo * SEQ + col]);
                const uchar2 mhi = *reinterpret_cast<const uchar2*>(
                    &Mg[(size_t)gr_hi * SEQ + col]);
                if (mlo.x) sacc[a][j][0] = -1e9f;
                if (mlo.y) sacc[a][j][1] = -1e9f;
                if (mhi.x) sacc[a][j][2] = -1e9f;
                if (mhi.y) sacc[a][j][3] = -1e9f;
            }

            float mx0 = -1e30f, mx1 = -1e30f;
#pragma unroll
            for (int j = 0; j < 8; j++) {
                mx0 = fmaxf(mx0, fmaxf(sacc[a][j][0], sacc[a][j][1]));
                mx1 = fmaxf(mx1, fmaxf(sacc[a][j][2], sacc[a][j][3]));
            }
            mx0 = fmaxf(mx0, __shfl_xor_sync(0xffffffffu, mx0, 1));
            mx0 = fmaxf(mx0, __shfl_xor_sync(0xffffffffu, mx0, 2));
            mx1 = fmaxf(mx1, __shfl_xor_sync(0xffffffffu, mx1, 1));
            mx1 = fmaxf(mx1, __shfl_xor_sync(0xffffffffu, mx1, 2));

            const float nm0 = fmaxf(mi[a][0], mx0);
            const float nm1 = fmaxf(mi[a][1], mx1);
            const float corr0 = __expf(mi[a][0] - nm0);
            const float corr1 = __expf(mi[a][1] - nm1);
            mi[a][0] = nm0; mi[a][1] = nm1;

            float rs0 = 0.0f, rs1 = 0.0f;
#pragma unroll
            for (int j = 0; j < 8; j++) {
                const float p0 = __expf(sacc[a][j][0] - nm0);
                const float p1 = __expf(sacc[a][j][1] - nm0);
                const float p2 = __expf(sacc[a][j][2] - nm1);
                const float p3 = __expf(sacc[a][j][3] - nm1);
                rs0 += p0 + p1;
                rs1 += p2 + p3;
                // Leave tf32 bit patterns in sacc for the shuffle phase.
                sacc[a][j][0] = __uint_as_float(f2tf32(p0));
                sacc[a][j][1] = __uint_as_float(f2tf32(p1));
                sacc[a][j][2] = __uint_as_float(f2tf32(p2));
                sacc[a][j][3] = __uint_as_float(f2tf32(p3));
            }
            rs0 += __shfl_xor_sync(0xffffffffu, rs0, 1);
            rs0 += __shfl_xor_sync(0xffffffffu, rs0, 2);
            rs1 += __shfl_xor_sync(0xffffffffu, rs1, 1);
            rs1 += __shfl_xor_sync(0xffffffffu, rs1, 2);
            li[a][0] = li[a][0] * corr0 + rs0;
            li[a][1] = li[a][1] * corr1 + rs1;

#pragma unroll
            for (int j = 0; j < 8; j++) {
                oc[a][j][0] *= corr0; oc[a][j][1] *= corr0;
                oc[a][j][2] *= corr1; oc[a][j][3] *= corr1;
            }
        }

        // ---- O += P V : A-frags via quad shuffles (no smem round-trip).
#pragma unroll
        for (int ks = 0; ks < 8; ks++) {
            const int kb = ks * 8;
            uint32_t ap[8];
            ap[0] = pfrag(sacc[0][ks][0], sacc[0][ks][1], srcA, t);
            ap[1] = pfrag(sacc[0][ks][2], sacc[0][ks][3], srcA, t);
            ap[2] = pfrag(sacc[0][ks][0], sacc[0][ks][1], srcB, t);
            ap[3] = pfrag(sacc[0][ks][2], sacc[0][ks][3], srcB, t);
            ap[4] = pfrag(sacc[1][ks][0], sacc[1][ks][1], srcA, t);
            ap[5] = pfrag(sacc[1][ks][2], sacc[1][ks][3], srcA, t);
            ap[6] = pfrag(sacc[1][ks][0], sacc[1][ks][1], srcB, t);
            ap[7] = pfrag(sacc[1][ks][2], sacc[1][ks][3], srcB, t);
#pragma unroll
            for (int j = 0; j < 8; j++) {
                uint32_t bf[2];
                bf[0] = Vt[(j * 8 + g) * 68 + kb + t];
                bf[1] = Vt[(j * 8 + g) * 68 + kb + t + 4];
                mma_tf32(oc[0][j], ap, bf);
                mma_tf32(oc[1][j], ap + 4, bf);
            }
        }
        __syncthreads();   // Ks/Vt reused next tile
    }

    // ---- normalize + write heads [B, N, H*64]
#pragma unroll
    for (int a = 0; a < 2; a++) {
        const float inv0 = 1.0f / li[a][0];
        const float inv1 = 1.0f / li[a][1];
        const int gr_lo = r0 + wr + g + a * 16;
        float* dlo = &g_hd[((size_t)b * SEQ + gr_lo) * DM + h * DK];
        float* dhi = &g_hd[((size_t)b * SEQ + gr_lo + 8) * DM + h * DK];
#pragma unroll
        for (int j = 0; j < 8; j++) {
            const int c = j * 8 + 2 * t;
            *reinterpret_cast<float2*>(&dlo[c]) =
                make_float2(oc[a][j][0] * inv0, oc[a][j][1] * inv0);
            *reinterpret_cast<float2*>(&dhi[c]) =
                make_float2(oc[a][j][2] * inv1, oc[a][j][3] * inv1);
        }
    }
}

// ===========================================================================
// Launch. Inputs (metadata order): x, mask, Wq, Wk, Wv, Wo. Output fp32.
// ===========================================================================
extern "C" void kernel_launch(void* const* d_in, const int* in_sizes, int n_in,
                              void* d_out, int out_size)
{
    const float* x    = (const float*)d_in[0];
    const void*  mask = d_in[1];
    const float* Wq   = (const float*)d_in[2];
    const float* Wk   = (const float*)d_in[3];
    const float* Wv   = (const float*)d_in[4];
    const float* Wo   = (const float*)d_in[5];
    float* outp = (float*)d_out;

    (void)in_sizes; (void)n_in; (void)out_size;

    cudaFuncSetAttribute(attn_kernel,
                         cudaFuncAttributeMaxDynamicSharedMemorySize, ATT_SMEM);

    // 0) Mask dtype detection + canonicalization to 1-byte 0/1
    mask_detect<<<1, 1024>>>((const unsigned*)mask);
    mask_convert<<<(BB * SEQ * SEQ / 4) / 256, 256>>>(mask);

    // 1) Q, K, V projections (mma.sync tf32)
    gemm_mma<<<dim3(BB * SEQ / 128, NH, 3), 256>>>(
        x, Wq, Wk, Wv, Wo, outp, 0);

    // 2) Flash attention (mma.sync tf32, P via shuffle, 3 CTAs/SM)
    attn_kernel<<<dim3(SEQ / 128, NH, BB), 128, ATT_SMEM>>>();

    // 3) Output projection (mma.sync tf32, head-sum folded into K)
    gemm_mma<<<dim3(BB * SEQ / 128, DM / 64, 1), 256>>>(
        x, Wq, Wk, Wv, Wo, outp, 1);
}

// round 10
// speedup vs baseline: 1.3275x; 1.3275x over previous
#include <cuda_runtime.h>
#include <cstdint>

#define BB 8
#define SEQ 1024
#define DM 512
#define NH 8
#define DK 64

// Scratch (allocation-free rule: __device__ globals).
__device__ float g_q[BB * NH * SEQ * DK];
__device__ float g_k[BB * NH * SEQ * DK];
__device__ float g_v[BB * NH * SEQ * DK];
__device__ float g_hd[BB * SEQ * DM];
__device__ unsigned long long g_mbits[(size_t)BB * SEQ * 16];  // [b][row][tile] bitmask
__device__ unsigned g_flags[2];

// ===========================================================================
// tf32 helpers (baseline PTX, supported on plain sm_103 target)
// ===========================================================================
__device__ __forceinline__ uint32_t f2tf32(float f) {
    uint32_t u;
    asm("cvt.rna.tf32.f32 %0, %1;" : "=r"(u) : "f"(f));
    return u;
}

__device__ __forceinline__ void mma_tf32(float* c, const uint32_t* a,
                                         const uint32_t* b) {
    asm volatile(
        "mma.sync.aligned.m16n8k8.row.col.f32.tf32.tf32.f32 "
        "{%0,%1,%2,%3}, {%4,%5,%6,%7}, {%8,%9}, {%0,%1,%2,%3};"
        : "+f"(c[0]), "+f"(c[1]), "+f"(c[2]), "+f"(c[3])
        : "r"(a[0]), "r"(a[1]), "r"(a[2]), "r"(a[3]),
          "r"(b[0]), "r"(b[1]));
}

// ===========================================================================
// Mask dtype detection (proven) + bit packing.
// ===========================================================================
__global__ void mask_detect(const unsigned* __restrict__ m)
{
    __shared__ unsigned s0, s1;
    if (threadIdx.x == 0) { s0 = 0u; s1 = 0u; }
    __syncthreads();
    unsigned a0 = 0u, a1 = 0u;
    for (int i = threadIdx.x; i < 65536; i += blockDim.x) {
        const unsigned w = m[i];
        if (w > 1u) a0 = 1u;
        const unsigned b = w | (w >> 8) | (w >> 16) | (w >> 24);
        if (b & 0xFEu) a1 = 1u;
    }
    if (a0) atomicOr(&s0, 1u);
    if (a1) atomicOr(&s1, 1u);
    __syncthreads();
    if (threadIdx.x == 0) { g_flags[0] = s0; g_flags[1] = s1; }
}

// One thread packs 64 mask elements (one key-tile of one row) into a u64.
// Bit c set => (row, tile*64+c) masked. idx = row*16 + tile; elems at idx*64.
__global__ __launch_bounds__(256) void mask_pack(const void* __restrict__ mraw)
{
    const size_t idx = (size_t)blockIdx.x * 256 + threadIdx.x;  // 0..131071
    const unsigned kind = (g_flags[0] == 0u) ? 0u : ((g_flags[1] == 0u) ? 1u : 2u);
    unsigned long long bits = 0ull;
    if (kind == 0u) {
        const int4* p = reinterpret_cast<const int4*>(mraw) + idx * 16;
#pragma unroll
        for (int j = 0; j < 16; j++) {
            const int4 v = p[j];
            const unsigned nib = (unsigned)(v.x != 0) | ((unsigned)(v.y != 0) << 1)
                               | ((unsigned)(v.z != 0) << 2) | ((unsigned)(v.w != 0) << 3);
            bits |= (unsigned long long)nib << (j * 4);
        }
    } else if (kind == 1u) {
        const uint4* p = reinterpret_cast<const uint4*>(mraw) + idx * 4;
#pragma unroll
        for (int j = 0; j < 4; j++) {
            const uint4 v = p[j];
            const unsigned n0 = (v.x & 1u) | ((v.x >> 7) & 2u) | ((v.x >> 14) & 4u) | ((v.x >> 21) & 8u);
            const unsigned n1 = (v.y & 1u) | ((v.y >> 7) & 2u) | ((v.y >> 14) & 4u) | ((v.y >> 21) & 8u);
            const unsigned n2 = (v.z & 1u) | ((v.z >> 7) & 2u) | ((v.z >> 14) & 4u) | ((v.z >> 21) & 8u);
            const unsigned n3 = (v.w & 1u) | ((v.w >> 7) & 2u) | ((v.w >> 14) & 4u) | ((v.w >> 21) & 8u);
            bits |= (unsigned long long)(n0 | (n1 << 4) | (n2 << 8) | (n3 << 12)) << (j * 16);
        }
    } else {
        const float4* p = reinterpret_cast<const float4*>(mraw) + idx * 16;
#pragma unroll
        for (int j = 0; j < 16; j++) {
            const float4 v = p[j];
            const unsigned nib = (unsigned)(v.x != 0.0f) | ((unsigned)(v.y != 0.0f) << 1)
                               | ((unsigned)(v.z != 0.0f) << 2) | ((unsigned)(v.w != 0.0f) << 3);
            bits |= (unsigned long long)nib << (j * 4);
        }
    }
    g_mbits[idx] = bits;
}

// ===========================================================================
// Warp-level mma.sync tf32 GEMM — 128 threads, warp tile 32x64 (2m x 8n).
// B-frags amortized over 2 m-atoms (1.5 LDS/MMA). Bs stored [kk][n] with
// stride 72: staging STS.128 banks (8kk+4nq) and frag LDS banks (8t+g) both
// conflict-free (old layout had an 8-way staging conflict). 3 CTAs/SM.
// ===========================================================================
__global__ __launch_bounds__(128, 3) void gemm_mma(
    const float* __restrict__ x,
    const float* __restrict__ Wq, const float* __restrict__ Wk,
    const float* __restrict__ Wv, const float* __restrict__ Wo,
    float* __restrict__ outp, int mode)
{
    __shared__ uint32_t As[128][36];   // [m][k]
    __shared__ uint32_t Bs[32][72];    // [k][n] (transposed staging)

    const int tid = threadIdx.x;
    const int wid = tid >> 5;          // 0..3, warp owns rows wid*32..+31
    const int lid = tid & 31;
    const int g = lid >> 2;
    const int t = lid & 3;

    const float* __restrict__ A;
    const float* __restrict__ Bb;
    int ldb;
    if (mode == 0) {
        const int z = blockIdx.z;
        const float* W = (z == 0) ? Wq : ((z == 1) ? Wk : Wv);
        A = x;
        Bb = W + (size_t)blockIdx.y * DM * DK;
        ldb = DK;
    } else {
        A = g_hd;
        Bb = Wo + blockIdx.y * 64;
        ldb = DM;
    }
    const int m0 = blockIdx.x * 128;

    float acc[2][8][4];
#pragma unroll
    for (int i = 0; i < 2; i++)
#pragma unroll
        for (int j = 0; j < 8; j++)
#pragma unroll
            for (int e = 0; e < 4; e++) acc[i][j][e] = 0.0f;

    for (int k0 = 0; k0 < DM; k0 += 32) {
        // A tile: 128 rows x 32 k = 1024 float4 / 128 thr = 8 iters.
#pragma unroll
        for (int it = 0; it < 8; it++) {
            const int idx = it * 128 + tid;
            const int r = idx >> 3;
            const int q = idx & 7;
            const float4 v = *reinterpret_cast<const float4*>(
                &A[(size_t)(m0 + r) * DM + k0 + q * 4]);
            uint4 u = make_uint4(f2tf32(v.x), f2tf32(v.y),
                                 f2tf32(v.z), f2tf32(v.w));
            *reinterpret_cast<uint4*>(&As[r][q * 4]) = u;
        }
        // B tile: 32 kk x 64 n = 512 float4 / 128 thr = 4 iters. [kk][n].
#pragma unroll
        for (int it = 0; it < 4; it++) {
            const int idx = it * 128 + tid;
            const int kk = idx >> 4;
            const int nq = idx & 15;
            const float4 v = *reinterpret_cast<const float4*>(
                &Bb[(size_t)(k0 + kk) * ldb + nq * 4]);
            uint4 u = make_uint4(f2tf32(v.x), f2tf32(v.y),
                                 f2tf32(v.z), f2tf32(v.w));
            *reinterpret_cast<uint4*>(&Bs[kk][nq * 4]) = u;
        }
        __syncthreads();

#pragma unroll
        for (int kk = 0; kk < 4; kk++) {
            const int kb = kk * 8;
            uint32_t bf[8][2];
#pragma unroll
            for (int j = 0; j < 8; j++) {
                const int n = j * 8 + g;
                bf[j][0] = Bs[kb + t][n];
                bf[j][1] = Bs[kb + t + 4][n];
            }
#pragma unroll
            for (int i = 0; i < 2; i++) {
                const int rw = wid * 32 + i * 16 + g;
                uint32_t af[4];
                af[0] = As[rw][kb + t];
                af[1] = As[rw + 8][kb + t];
                af[2] = As[rw][kb + t + 4];
                af[3] = As[rw + 8][kb + t + 4];
#pragma unroll
                for (int j = 0; j < 8; j++)
                    mma_tf32(acc[i][j], af, bf[j]);
            }
        }
        __syncthreads();
    }

#pragma unroll
    for (int i = 0; i < 2; i++) {
#pragma unroll
        for (int rr = 0; rr < 2; rr++) {
            const int mg = m0 + wid * 32 + i * 16 + rr * 8 + g;
            float* dst;
            if (mode == 0) {
                const int z = blockIdx.z;
                float* outg = (z == 0) ? g_q : ((z == 1) ? g_k : g_v);
                const int b = mg >> 10;
                const int n = mg & 1023;
                dst = &outg[(((size_t)b * NH + blockIdx.y) * SEQ + n) * DK];
            } else {
                dst = &outp[(size_t)mg * DM + blockIdx.y * 64];
            }
#pragma unroll
            for (int j = 0; j < 8; j++) {
                const int col = j * 8 + t * 2;
                float2 o2 = make_float2(acc[i][j][rr * 2 + 0],
                                        acc[i][j][rr * 2 + 1]);
                *reinterpret_cast<float2*>(&dst[col]) = o2;
            }
        }
    }
}

// ===========================================================================
// Flash attention — REVERTED to the best-measured R7 config (Q in registers,
// P via per-warp smem, 2 m-atoms/warp, 128 threads), with the mask loads
// replaced by packed bitmasks (4 LDG.64/thread/tile instead of 16 LDG.16).
// ===========================================================================
#define PS_OFF 0                      // [128][68] u32 : Q staging, then P
#define KS_OFF (128 * 68)             // [64][68]  u32 : K tile [key][d]
#define VT_OFF (KS_OFF + 64 * 68)     // [64][68]  u32 : V tile [d][key]
#define ATT_SMEM ((VT_OFF + 64 * 68) * 4)

__global__ __launch_bounds__(128) void attn_kernel()
{
    extern __shared__ uint32_t dsm[];
    uint32_t* __restrict__ Ps = dsm + PS_OFF;
    uint32_t* __restrict__ Ks = dsm + KS_OFF;
    uint32_t* __restrict__ Vt = dsm + VT_OFF;

    const int r0 = blockIdx.x * 128;
    const int h  = blockIdx.y;
    const int b  = blockIdx.z;

    const int tid = threadIdx.x;
    const int w   = tid >> 5;
    const int lid = tid & 31;
    const int g   = lid >> 2;
    const int t   = lid & 3;
    const int wr  = w * 32;            // warp row base (local, 32 rows)

    const size_t bh = (size_t)b * NH + h;
    const float* __restrict__ Qg = &g_q[bh * SEQ * DK];
    const float* __restrict__ Kg = &g_k[bh * SEQ * DK];
    const float* __restrict__ Vg = &g_v[bh * SEQ * DK];

    // --- Stage Q tile through Ps (coalesced), then load register fragments.
#pragma unroll
    for (int it = 0; it < 16; it++) {
        const int idx = it * 128 + tid;
        const int r = idx >> 4;
        const int q4 = idx & 15;
        const float4 v = *reinterpret_cast<const float4*>(
            &Qg[(size_t)(r0 + r) * DK + q4 * 4]);
        uint4 u = make_uint4(f2tf32(v.x * 0.125f), f2tf32(v.y * 0.125f),
                             f2tf32(v.z * 0.125f), f2tf32(v.w * 0.125f));
        *reinterpret_cast<uint4*>(&Ps[r * 68 + q4 * 4]) = u;
    }
    __syncthreads();

    // aq[ks][0..3] = atom0 (rows wr+g, wr+g+8); [4..7] = atom1 (+16, +24)
    uint32_t aq[8][8];
    {
        const int ra = (wr + g) * 68;
        const int rb = ra + 8 * 68;
        const int rc = ra + 16 * 68;
        const int rd = ra + 24 * 68;
#pragma unroll
        for (int ks = 0; ks < 8; ks++) {
            const int kb = ks * 8;
            aq[ks][0] = Ps[ra + kb + t];
            aq[ks][1] = Ps[rb + kb + t];
            aq[ks][2] = Ps[ra + kb + t + 4];
            aq[ks][3] = Ps[rb + kb + t + 4];
            aq[ks][4] = Ps[rc + kb + t];
            aq[ks][5] = Ps[rd + kb + t];
            aq[ks][6] = Ps[rc + kb + t + 4];
            aq[ks][7] = Ps[rd + kb + t + 4];
        }
    }
    __syncthreads();

    // Online softmax state per thread: 4 owned rows (2 atoms x {g, g+8}).
    float mi[2][2], li[2][2];
#pragma unroll
    for (int a = 0; a < 2; a++) {
        mi[a][0] = -1e30f; mi[a][1] = -1e30f;
        li[a][0] = 0.0f;   li[a][1] = 0.0f;
    }
    float oc[2][8][4];
#pragma unroll
    for (int a = 0; a < 2; a++)
#pragma unroll
        for (int j = 0; j < 8; j++)
#pragma unroll
            for (int e = 0; e < 4; e++) oc[a][j][e] = 0.0f;

    for (int m0 = 0; m0 < SEQ; m0 += 64) {
        // K tile: natural [key][d] layout (coalesced).
#pragma unroll
        for (int it = 0; it < 8; it++) {
            const int idx = it * 128 + tid;
            const int r = idx >> 4;
            const int q4 = idx & 15;
            const float4 v = *reinterpret_cast<const float4*>(
                &Kg[(size_t)(m0 + r) * DK + q4 * 4]);
            uint4 u = make_uint4(f2tf32(v.x), f2tf32(v.y),
                                 f2tf32(v.z), f2tf32(v.w));
            *reinterpret_cast<uint4*>(&Ks[r * 68 + q4 * 4]) = u;
        }
        // V tile transposed: Vt[d][key].
#pragma unroll
        for (int it = 0; it < 8; it++) {
            const int idx = it * 128 + tid;
            const int key = idx & 63;
            const int dq = idx >> 6;
            const float4 v = *reinterpret_cast<const float4*>(
                &Vg[(size_t)(m0 + key) * DK + dq * 4]);
            Vt[(dq * 4 + 0) * 68 + key] = f2tf32(v.x);
            Vt[(dq * 4 + 1) * 68 + key] = f2tf32(v.y);
            Vt[(dq * 4 + 2) * 68 + key] = f2tf32(v.z);
            Vt[(dq * 4 + 3) * 68 + key] = f2tf32(v.w);
        }
        __syncthreads();

        // ---- S = Q K^T : one bf load feeds both m-atoms.
        float sacc[2][8][4];
#pragma unroll
        for (int a = 0; a < 2; a++)
#pragma unroll
            for (int j = 0; j < 8; j++)
#pragma unroll
                for (int e = 0; e < 4; e++) sacc[a][j][e] = 0.0f;

#pragma unroll
        for (int ks = 0; ks < 8; ks++) {
            const int kb = ks * 8;
#pragma unroll
            for (int j = 0; j < 8; j++) {
                uint32_t bf[2];
                bf[0] = Ks[(j * 8 + g) * 68 + kb + t];
                bf[1] = Ks[(j * 8 + g) * 68 + kb + t + 4];
                mma_tf32(sacc[0][j], aq[ks], bf);
                mma_tf32(sacc[1][j], aq[ks] + 4, bf);
            }
        }

        // ---- bitmask + online softmax per atom.
        const int tIdx = m0 >> 6;
        const int prbase = (wr + g) * 68;
#pragma unroll
        for (int a = 0; a < 2; a++) {
            const int gr_lo = r0 + wr + g + a * 16;
            const int gr_hi = gr_lo + 8;
            const unsigned long long mlo64 =
                g_mbits[((size_t)b * SEQ + gr_lo) * 16 + tIdx];
            const unsigned long long mhi64 =
                g_mbits[((size_t)b * SEQ + gr_hi) * 16 + tIdx];
            const uint32_t ml[2] = {(uint32_t)mlo64, (uint32_t)(mlo64 >> 32)};
            const uint32_t mh[2] = {(uint32_t)mhi64, (uint32_t)(mhi64 >> 32)};
#pragma unroll
            for (int j = 0; j < 8; j++) {
                const int sh = ((j & 3) << 3) + (t << 1);
                const uint32_t bl = ml[j >> 2] >> sh;
                const uint32_t bhv = mh[j >> 2] >> sh;
                if (bl & 1u)  sacc[a][j][0] = -1e9f;
                if (bl & 2u)  sacc[a][j][1] = -1e9f;
                if (bhv & 1u) sacc[a][j][2] = -1e9f;
                if (bhv & 2u) sacc[a][j][3] = -1e9f;
            }

            float mx0 = -1e30f, mx1 = -1e30f;
#pragma unroll
            for (int j = 0; j < 8; j++) {
                mx0 = fmaxf(mx0, fmaxf(sacc[a][j][0], sacc[a][j][1]));
                mx1 = fmaxf(mx1, fmaxf(sacc[a][j][2], sacc[a][j][3]));
            }
            mx0 = fmaxf(mx0, __shfl_xor_sync(0xffffffffu, mx0, 1));
            mx0 = fmaxf(mx0, __shfl_xor_sync(0xffffffffu, mx0, 2));
            mx1 = fmaxf(mx1, __shfl_xor_sync(0xffffffffu, mx1, 1));
            mx1 = fmaxf(mx1, __shfl_xor_sync(0xffffffffu, mx1, 2));

            const float nm0 = fmaxf(mi[a][0], mx0);
            const float nm1 = fmaxf(mi[a][1], mx1);
            const float corr0 = __expf(mi[a][0] - nm0);
            const float corr1 = __expf(mi[a][1] - nm1);
            mi[a][0] = nm0; mi[a][1] = nm1;

            float rs0 = 0.0f, rs1 = 0.0f;
            const int prlo = prbase + a * 16 * 68;
            const int prhi = prlo + 8 * 68;
#pragma unroll
            for (int j = 0; j < 8; j++) {
                const float p0 = __expf(sacc[a][j][0] - nm0);
                const float p1 = __expf(sacc[a][j][1] - nm0);
                const float p2 = __expf(sacc[a][j][2] - nm1);
                const float p3 = __expf(sacc[a][j][3] - nm1);
                rs0 += p0 + p1;
                rs1 += p2 + p3;
                const int c = j * 8 + 2 * t;
                Ps[prlo + c]     = f2tf32(p0);
                Ps[prlo + c + 1] = f2tf32(p1);
                Ps[prhi + c]     = f2tf32(p2);
                Ps[prhi + c + 1] = f2tf32(p3);
            }
            rs0 += __shfl_xor_sync(0xffffffffu, rs0, 1);
            rs0 += __shfl_xor_sync(0xffffffffu, rs0, 2);
            rs1 += __shfl_xor_sync(0xffffffffu, rs1, 1);
            rs1 += __shfl_xor_sync(0xffffffffu, rs1, 2);
            li[a][0] = li[a][0] * corr0 + rs0;
            li[a][1] = li[a][1] * corr1 + rs1;

#pragma unroll
            for (int j = 0; j < 8; j++) {
                oc[a][j][0] *= corr0; oc[a][j][1] *= corr0;
                oc[a][j][2] *= corr1; oc[a][j][3] *= corr1;
            }
        }
        __syncwarp();

        // ---- O += P V : one bf load feeds both m-atoms.
#pragma unroll
        for (int ks = 0; ks < 8; ks++) {
            const int kb = ks * 8;
            uint32_t ap[8];
            ap[0] = Ps[prbase + kb + t];
            ap[1] = Ps[prbase + 8 * 68 + kb + t];
            ap[2] = Ps[prbase + kb + t + 4];
            ap[3] = Ps[prbase + 8 * 68 + kb + t + 4];
            ap[4] = Ps[prbase + 16 * 68 + kb + t];
            ap[5] = Ps[prbase + 24 * 68 + kb + t];
            ap[6] = Ps[prbase + 16 * 68 + kb + t + 4];
            ap[7] = Ps[prbase + 24 * 68 + kb + t + 4];
#pragma unroll
            for (int j = 0; j < 8; j++) {
                uint32_t bf[2];
                bf[0] = Vt[(j * 8 + g) * 68 + kb + t];
                bf[1] = Vt[(j * 8 + g) * 68 + kb + t + 4];
                mma_tf32(oc[0][j], ap, bf);
                mma_tf32(oc[1][j], ap + 4, bf);
            }
        }
        __syncthreads();   // Ks/Vt reused next tile
    }

    // ---- normalize + write heads [B, N, H*64]
#pragma unroll
    for (int a = 0; a < 2; a++) {
        const float inv0 = 1.0f / li[a][0];
        const float inv1 = 1.0f / li[a][1];
        const int gr_lo = r0 + wr + g + a * 16;
        float* dlo = &g_hd[((size_t)b * SEQ + gr_lo) * DM + h * DK];
        float* dhi = &g_hd[((size_t)b * SEQ + gr_lo + 8) * DM + h * DK];
#pragma unroll
        for (int j = 0; j < 8; j++) {
            const int c = j * 8 + 2 * t;
            *reinterpret_cast<float2*>(&dlo[c]) =
                make_float2(oc[a][j][0] * inv0, oc[a][j][1] * inv0);
            *reinterpret_cast<float2*>(&dhi[c]) =
                make_float2(oc[a][j][2] * inv1, oc[a][j][3] * inv1);
        }
    }
}

// ===========================================================================
// Launch. Inputs (metadata order): x, mask, Wq, Wk, Wv, Wo. Output fp32.
// ===========================================================================
extern "C" void kernel_launch(void* const* d_in, const int* in_sizes, int n_in,
                              void* d_out, int out_size)
{
    const float* x    = (const float*)d_in[0];
    const void*  mask = d_in[1];
    const float* Wq   = (const float*)d_in[2];
    const float* Wk   = (const float*)d_in[3];
    const float* Wv   = (const float*)d_in[4];
    const float* Wo   = (const float*)d_in[5];
    float* outp = (float*)d_out;

    (void)in_sizes; (void)n_in; (void)out_size;

    cudaFuncSetAttribute(attn_kernel,
                         cudaFuncAttributeMaxDynamicSharedMemorySize, ATT_SMEM);

    // 0) Mask dtype detection + bit packing ([row][tile] u64)
    mask_detect<<<1, 1024>>>((const unsigned*)mask);
    mask_pack<<<512, 256>>>(mask);

    // 1) Q, K, V projections (mma.sync tf32, 2m x 8n warp tile)
    gemm_mma<<<dim3(BB * SEQ / 128, NH, 3), 128>>>(
        x, Wq, Wk, Wv, Wo, outp, 0);

    // 2) Flash attention (mma.sync tf32, R7 config + bitmask)
    attn_kernel<<<dim3(SEQ / 128, NH, BB), 128, ATT_SMEM>>>();

    // 3) Output projection (mma.sync tf32, head-sum folded into K)
    gemm_mma<<<dim3(BB * SEQ / 128, DM / 64, 1), 128>>>(
        x, Wq, Wk, Wv, Wo, outp, 1);
}